// round 11
// baseline (speedup 1.0000x reference)
#include <cuda_runtime.h>
#include <cuda_bf16.h>

// Problem constants (from reference)
#define C_L0 0.05f
#define C_D  0.0075f
#define C_DS 0.005f

#define TPB 256          // batch elems per block == threads per block
#define ROWF (TPB * 14)  // floats per staged time-row (3584)
#define ROWF4 (ROWF / 4) // float4s per row (896)

// Closed-form kernel: the ODE y' = f(y) with constant (ux,uy) is linear with
// constant generator w_hat (axis w=(ux,uy,0)), so the RK4 trajectory is
// (to ~8e-6 abs, vs 1e-3 tolerance) the exact flow:
//   R(s) = I + sin(th)/w * w_hat + (1-cos(th))/w^2 * w_hat^2,  th = |w| s
//   r(s) = ( (1-cos th)/w^2 * uy, -(1-cos th)/w^2 * ux, s - (th - sin th)/|w| )
// Row (seg,t) is the state after n_eff = seg*nsteps + min(t,nsteps) steps
// (frozen beyond nsteps by the reference's masking; both segments use
// actions[:,0:3] due to the reference's end-of-loop update quirk).
// Every output row is independent -> one CTA per (row, 256-batch chunk),
// pure streaming stores.
__global__ void __launch_bounds__(TPB)
ode_forward_kernel(const float* __restrict__ act, float* __restrict__ out, int B, int T) {
    __shared__ __align__(16) float sbuf[ROWF];

    int row = blockIdx.x;            // 0 .. 2T-1
    int seg = (row >= T) ? 1 : 0;
    int t   = row - seg * T;

    int b0 = blockIdx.y * TPB;
    int b  = b0 + threadIdx.x;
    bool active = (b < B);
    bool fullblk = (b0 + TPB <= B);
    int nvalid = min(TPB, B - b0);

    float a0 = 0.f, a1 = 0.f, a2 = 0.f;
    if (active) {
        a0 = __ldg(&act[(size_t)b * 6 + 0]);
        a1 = __ldg(&act[(size_t)b * 6 + 1]);
        a2 = __ldg(&act[(size_t)b * 6 + 2]);
    }

    float l  = C_L0 + a0;
    float ux = a2 / (-(l * C_D));
    float uy = a1 / (l * C_D);
    int length = (int)floorf(l / C_DS);
    int nsteps = min(length, T - 1);

    int n_eff = seg * nsteps + min(t, nsteps);
    float s = (float)n_eff * C_DS;

    float w2 = fmaf(ux, ux, uy * uy);
    float w  = sqrtf(w2);
    float th = w * s;
    float sth, cth;
    __sincosf(th, &sth, &cth);

    float A, Bc, Cz;                  // sin/w, (1-cos)/w^2, (th-sin)/w^3
    if (th > 1e-3f) {
        A  = sth / w;
        Bc = (1.f - cth) / w2;
        Cz = (th - sth) / (w2 * w);
    } else {                          // Taylor (w or s ~ 0)
        float t2 = th * th;
        A  = s * (1.f - t2 * (1.f / 6.f));
        Bc = 0.5f * s * s * (1.f - t2 * (1.f / 12.f));
        Cz = s * s * s * (1.f / 6.f) * (1.f - t2 * (1.f / 20.f));
        cth = 1.f - 0.5f * t2;
    }

    float y[12];
    y[0]  = Bc * uy;                  // r.x
    y[1]  = -Bc * ux;                 // r.y
    y[2]  = s - Cz * w2;              // r.z
    y[3]  = 1.f - Bc * uy * uy;       // R00
    y[4]  = Bc * ux * uy;             // R01
    y[5]  = A * uy;                   // R02
    y[6]  = y[4];                     // R10
    y[7]  = 1.f - Bc * ux * ux;       // R11
    y[8]  = -A * ux;                  // R12
    y[9]  = -A * uy;                  // R20
    y[10] = A * ux;                   // R21
    y[11] = cth;                      // R22

    // Stage in output-linear layout (float2 STS, conflict-free).
    float2* srow = (float2*)&sbuf[threadIdx.x * 14];
    if (active) {
        srow[0] = make_float2(y[0],  y[1]);
        srow[1] = make_float2(y[2],  y[3]);
        srow[2] = make_float2(y[4],  y[5]);
        srow[3] = make_float2(y[6],  y[7]);
        srow[4] = make_float2(y[8],  y[9]);
        srow[5] = make_float2(y[10], y[11]);
        srow[6] = make_float2(ux,    uy);
    }
    __syncthreads();

    size_t base = ((size_t)row * (size_t)B + (size_t)b0) * 14;
    if (fullblk) {
        const float4* s4 = (const float4*)sbuf;
        float4* o4 = (float4*)(out + base);
#pragma unroll
        for (int i = 0; i < 3; i++)
            o4[threadIdx.x + i * TPB] = s4[threadIdx.x + i * TPB];
        if (threadIdx.x < (ROWF4 - 3 * TPB))
            o4[threadIdx.x + 3 * TPB] = s4[threadIdx.x + 3 * TPB];
    } else {
        int rowfloats = nvalid * 14;
        for (int f = threadIdx.x; f < rowfloats; f += TPB)
            out[base + f] = sbuf[f];
    }
}

extern "C" void kernel_launch(void* const* d_in, const int* in_sizes, int n_in,
                              void* d_out, int out_size) {
    const float* actions = (const float*)d_in[0];
    float* out = (float*)d_out;

    int B = in_sizes[0] / 6;                 // 262144
    int T = out_size / (2 * B * 14);         // time steps per segment (incl. t=0)

    dim3 grid(2 * T, (B + TPB - 1) / TPB);
    ode_forward_kernel<<<grid, TPB>>>(actions, out, B, T);
}

// round 13
// speedup vs baseline: 1.0966x; 1.0966x over previous
#include <cuda_runtime.h>
#include <cuda_bf16.h>

// Problem constants (from reference)
#define C_L0 0.05f
#define C_D  0.0075f
#define C_DS 0.005f

#define TPB 256          // batch elems per block == threads per block
#define ROWF (TPB * 14)  // floats per staged time-row (3584)
#define ROWF4 (ROWF / 4) // float4s per row (896)

// Closed-form trajectory: with (ux,uy) constant (both segments use
// actions[:,0:3] due to the reference's end-of-loop update quirk), the ODE is
// linear with constant generator w_hat, axis w=(ux,uy,0):
//   R(s) = I + sin(th)/w * w_hat + (1-cos th)/w^2 * w_hat^2,  th = |w| s
//   r(s) = ( (1-cos th)/w^2 * uy, -(1-cos th)/w^2 * ux, s - (th - sin th)/|w| )
// Row (seg,t) = state after n_eff = seg*nsteps + min(t,nsteps) steps (frozen
// beyond nsteps by the reference's masking). RK4-vs-exact deviation ~1e-5 abs,
// far under the 1e-3 tolerance.
//
// Structure: one CTA per 256-element batch chunk; actions loaded ONCE; loop
// over all 2T rows computing the closed form (~40 flops/row), staging in
// output-linear smem (double-buffered, 1 sync/row), draining with float4
// identity copies (coalesced 128B-line stores, evict-first).
__global__ void __launch_bounds__(TPB)
ode_forward_kernel(const float* __restrict__ act, float* __restrict__ out, int B, int T) {
    __shared__ __align__(16) float sbuf[2][ROWF];

    int b0 = blockIdx.x * TPB;
    int b  = b0 + threadIdx.x;
    bool active = (b < B);
    bool fullblk = (b0 + TPB <= B);
    int nvalid = min(TPB, B - b0);

    float a0 = 0.f, a1 = 0.f, a2 = 0.f;
    if (active) {
        a0 = __ldg(&act[(size_t)b * 6 + 0]);
        a1 = __ldg(&act[(size_t)b * 6 + 1]);
        a2 = __ldg(&act[(size_t)b * 6 + 2]);
    }

    float l  = C_L0 + a0;
    float ux = a2 / (-(l * C_D));
    float uy = a1 / (l * C_D);
    int nsteps = min((int)floorf(l / C_DS), T - 1);

    float w2 = fmaf(ux, ux, uy * uy);
    float w  = sqrtf(w2);
    float inv_w2 = 1.f / w2;          // actions ~U(0,0.01)*scale -> w >> 0
    float uxuy   = ux * uy;

    int buf = 0;
    int T2 = 2 * T;

    for (int row = 0; row < T2; row++) {
        int seg = (row >= T) ? 1 : 0;
        int t   = row - seg * T;
        int n_eff = seg * nsteps + min(t, nsteps);
        float s = (float)n_eff * C_DS;

        float th = w * s;
        float sth, cth;
        __sincosf(th, &sth, &cth);

        float A, Bc, Cz;              // sin/w, (1-cos)/w^2, (th-sin)/w^3
        if (th > 1e-3f) {
            A  = sth * (w * inv_w2);  // sth/w
            Bc = (1.f - cth) * inv_w2;
            Cz = (th - sth) * inv_w2 * (w * inv_w2);
        } else {                      // Taylor fallback (tiny/zero angle)
            float t2 = th * th;
            A  = s * (1.f - t2 * (1.f / 6.f));
            Bc = 0.5f * s * s * (1.f - t2 * (1.f / 12.f));
            Cz = s * s * s * (1.f / 6.f) * (1.f - t2 * (1.f / 20.f));
            cth = 1.f - 0.5f * t2;
        }

        // Stage in output-linear layout (float2 STS, conflict-free:
        // bank(L,j) = (L*14 + 2j) % 32 distinct within 16-lane phases).
        float2* srow = (float2*)&sbuf[buf][threadIdx.x * 14];
        if (active) {
            srow[0] = make_float2(Bc * uy,             -Bc * ux);      // r.x, r.y
            srow[1] = make_float2(s - Cz * w2,         1.f - Bc * uy * uy); // r.z, R00
            srow[2] = make_float2(Bc * uxuy,           A * uy);        // R01, R02
            srow[3] = make_float2(Bc * uxuy,           1.f - Bc * ux * ux); // R10, R11
            srow[4] = make_float2(-A * ux,             -A * uy);       // R12, R20
            srow[5] = make_float2(A * ux,              cth);           // R21, R22
            srow[6] = make_float2(ux,                  uy);
        }
        __syncthreads();   // stage visible; also guards restage vs copy(row-2)

        size_t base = ((size_t)row * (size_t)B + (size_t)b0) * 14;
        if (fullblk) {
            const float4* s4 = (const float4*)&sbuf[buf][0];
            float4* o4 = (float4*)(out + base);
#pragma unroll
            for (int i = 0; i < 3; i++)
                __stcs(&o4[threadIdx.x + i * TPB], s4[threadIdx.x + i * TPB]);
            if (threadIdx.x < (ROWF4 - 3 * TPB))
                __stcs(&o4[threadIdx.x + 3 * TPB], s4[threadIdx.x + 3 * TPB]);
        } else {
            int rowfloats = nvalid * 14;
            for (int f = threadIdx.x; f < rowfloats; f += TPB)
                out[base + f] = sbuf[buf][f];
        }
        buf ^= 1;
    }
}

extern "C" void kernel_launch(void* const* d_in, const int* in_sizes, int n_in,
                              void* d_out, int out_size) {
    const float* actions = (const float*)d_in[0];
    float* out = (float*)d_out;

    int B = in_sizes[0] / 6;                 // 262144
    int T = out_size / (2 * B * 14);         // time steps per segment (incl. t=0)

    int blocks = (B + TPB - 1) / TPB;
    ode_forward_kernel<<<blocks, TPB>>>(actions, out, B, T);
}

// round 14
// speedup vs baseline: 1.1374x; 1.0372x over previous
#include <cuda_runtime.h>
#include <cuda_bf16.h>

// Problem constants (from reference)
#define C_L0 0.05f
#define C_D  0.0075f
#define C_DS 0.005f

#define TPB 256            // batch elems per block == threads per block
#define ROWF (TPB * 14)    // floats per staged time-row (3584)
#define WSLICE4 (32 * 14 / 4)  // float4s per warp slice per row (112)

// Closed-form trajectory: with (ux,uy) constant (both segments use
// actions[:,0:3] due to the reference's end-of-loop update quirk), the ODE is
// linear with constant generator w_hat, axis w=(ux,uy,0):
//   R(s) = I + sin(th)/w * w_hat + (1-cos th)/w^2 * w_hat^2,  th = |w| s
//   r(s) = ( (1-cos th)/w^2 * uy, -(1-cos th)/w^2 * ux, s - (th - sin th)/|w| )
// Row (seg,t) = state after n_eff = seg*nsteps + min(t,nsteps) steps (frozen
// beyond nsteps by the reference's masking). Deviation from RK4 ~1e-5 abs,
// far under the 1e-3 tolerance.
//
// Structure: warp-AUTONOMOUS pipelining. Each warp owns 32 batch elems whose
// per-row output slice is a contiguous 1792B gmem region. Stage warp slice in
// smem (output-linear), __syncwarp, drain with float4 identity copy, repeat.
// No block-wide barriers -> warps never convoy, stores stay dense.
__global__ void __launch_bounds__(TPB)
ode_forward_kernel(const float* __restrict__ act, float* __restrict__ out, int B, int T) {
    __shared__ __align__(16) float sbuf[ROWF];   // single buffer; warp-private slices

    int b0 = blockIdx.x * TPB;
    int b  = b0 + threadIdx.x;
    int wid  = threadIdx.x >> 5;
    int lane = threadIdx.x & 31;
    bool active = (b < B);

    float a0 = 0.f, a1 = 0.f, a2 = 0.f;
    if (active) {
        a0 = __ldg(&act[(size_t)b * 6 + 0]);
        a1 = __ldg(&act[(size_t)b * 6 + 1]);
        a2 = __ldg(&act[(size_t)b * 6 + 2]);
    }

    float l  = C_L0 + a0;
    float ux = a2 / (-(l * C_D));
    float uy = a1 / (l * C_D);
    int nsteps = min((int)floorf(l / C_DS), T - 1);

    float w2 = fmaf(ux, ux, uy * uy);
    float w  = sqrtf(w2);
    float inv_w2 = 1.f / w2;          // actions ~U(0,1)*0.01 -> w >> 0 generically
    float uxuy   = ux * uy;

    // Warp-private smem slice: batch-linear within the block's row image.
    float2* srow = (float2*)&sbuf[(size_t)threadIdx.x * 14];
    const float4* wslice4 = (const float4*)&sbuf[(size_t)wid * 32 * 14];

    // Number of this warp's batch elems that are valid (for tail block).
    int wb0 = b0 + wid * 32;
    int wvalid = min(32, max(0, B - wb0));
    bool wfull = (wvalid == 32);

    int T2 = 2 * T;
    for (int row = 0; row < T2; row++) {
        int seg = (row >= T) ? 1 : 0;
        int t   = row - seg * T;
        int n_eff = seg * nsteps + min(t, nsteps);
        float s = (float)n_eff * C_DS;

        float th = w * s;
        float sth, cth;
        __sincosf(th, &sth, &cth);

        float A, Bc, Cz;              // sin/w, (1-cos)/w^2, (th-sin)/w^3
        if (th > 1e-3f) {
            A  = sth * (w * inv_w2);
            Bc = (1.f - cth) * inv_w2;
            Cz = (th - sth) * inv_w2 * (w * inv_w2);
        } else {                      // Taylor fallback (tiny/zero angle)
            float t2 = th * th;
            A  = s * (1.f - t2 * (1.f / 6.f));
            Bc = 0.5f * s * s * (1.f - t2 * (1.f / 12.f));
            Cz = s * s * s * (1.f / 6.f) * (1.f - t2 * (1.f / 20.f));
            cth = 1.f - 0.5f * t2;
        }

        // Protect previous row's drain reads before re-staging (warp-local).
        __syncwarp();

        if (active) {
            srow[0] = make_float2(Bc * uy,        -Bc * ux);            // r.x, r.y
            srow[1] = make_float2(s - Cz * w2,    1.f - Bc * uy * uy);  // r.z, R00
            srow[2] = make_float2(Bc * uxuy,      A * uy);              // R01, R02
            srow[3] = make_float2(Bc * uxuy,      1.f - Bc * ux * ux);  // R10, R11
            srow[4] = make_float2(-A * ux,        -A * uy);             // R12, R20
            srow[5] = make_float2(A * ux,         cth);                 // R21, R22
            srow[6] = make_float2(ux,             uy);
        }
        __syncwarp();   // warp's slice staged

        // Drain warp slice: 112 float4 = 3*32 + 16, contiguous in gmem.
        size_t base = ((size_t)row * (size_t)B + (size_t)wb0) * 14;
        if (wfull) {
            float4* o4 = (float4*)(out + base);
#pragma unroll
            for (int i = 0; i < 3; i++)
                __stcs(&o4[lane + i * 32], wslice4[lane + i * 32]);
            if (lane < (WSLICE4 - 96))
                __stcs(&o4[lane + 96], wslice4[lane + 96]);
        } else if (wvalid > 0) {
            const float* ws = (const float*)wslice4;
            int rowfloats = wvalid * 14;
            for (int f = lane; f < rowfloats; f += 32)
                out[base + f] = ws[f];
        }
    }
}

extern "C" void kernel_launch(void* const* d_in, const int* in_sizes, int n_in,
                              void* d_out, int out_size) {
    const float* actions = (const float*)d_in[0];
    float* out = (float*)d_out;

    int B = in_sizes[0] / 6;                 // 262144
    int T = out_size / (2 * B * 14);         // time steps per segment (incl. t=0)

    int blocks = (B + TPB - 1) / TPB;
    ode_forward_kernel<<<blocks, TPB>>>(actions, out, B, T);
}

// round 15
// speedup vs baseline: 1.2267x; 1.0786x over previous
#include <cuda_runtime.h>
#include <cuda_bf16.h>

// Problem constants (from reference)
#define C_L0 0.05f
#define C_D  0.0075f
#define C_DS 0.005f

#define TPB 256            // batch elems per block == threads per block
#define ROWF (TPB * 14)    // floats per staged time-row (3584)
#define WSLICE4 (32 * 14 / 4)  // float4s per warp slice per row (112)
#define NSPLIT 4           // row-range splits per batch chunk (tail-wave fix)

// Closed-form trajectory: with (ux,uy) constant (both segments use
// actions[:,0:3] due to the reference's end-of-loop update quirk), the ODE is
// linear with constant generator w_hat, axis w=(ux,uy,0):
//   R(s) = I + sin(th)/w * w_hat + (1-cos th)/w^2 * w_hat^2,  th = |w| s
//   r(s) = ( (1-cos th)/w^2 * uy, -(1-cos th)/w^2 * ux, s - (th - sin th)/|w| )
// Row (seg,t) = state after n_eff = seg*nsteps + min(t,nsteps) steps (frozen
// beyond nsteps by the reference's masking). Deviation from RK4 ~1e-5 abs,
// far under the 1e-3 tolerance.
//
// Structure: warp-autonomous pipelining (no block barriers), and the 2T rows
// are SPLIT across NSPLIT CTAs per batch chunk so the grid runs in ~7 dense
// waves instead of ~2 (the last partial wave was idling ~15% of the chip).
__global__ void __launch_bounds__(TPB)
ode_forward_kernel(const float* __restrict__ act, float* __restrict__ out, int B, int T) {
    __shared__ __align__(16) float sbuf[ROWF];   // single buffer; warp-private slices

    int b0 = blockIdx.x * TPB;
    int b  = b0 + threadIdx.x;
    int wid  = threadIdx.x >> 5;
    int lane = threadIdx.x & 31;
    bool active = (b < B);

    float a0 = 0.f, a1 = 0.f, a2 = 0.f;
    if (active) {
        a0 = __ldg(&act[(size_t)b * 6 + 0]);
        a1 = __ldg(&act[(size_t)b * 6 + 1]);
        a2 = __ldg(&act[(size_t)b * 6 + 2]);
    }

    float l  = C_L0 + a0;
    float ux = a2 / (-(l * C_D));
    float uy = a1 / (l * C_D);
    int nsteps = min((int)floorf(l / C_DS), T - 1);

    float w2 = fmaf(ux, ux, uy * uy);
    float w  = sqrtf(w2);
    float inv_w2 = 1.f / w2;          // actions ~U(0,1)*0.01 -> w >> 0 generically
    float uxuy   = ux * uy;

    // Warp-private smem slice: batch-linear within the block's row image.
    float2* srow = (float2*)&sbuf[(size_t)threadIdx.x * 14];
    const float4* wslice4 = (const float4*)&sbuf[(size_t)wid * 32 * 14];

    int wb0 = b0 + wid * 32;
    int wvalid = min(32, max(0, B - wb0));
    bool wfull = (wvalid == 32);

    // This CTA's row range.
    int T2 = 2 * T;
    int rows_per = (T2 + NSPLIT - 1) / NSPLIT;
    int r0   = blockIdx.y * rows_per;
    int rend = min(r0 + rows_per, T2);

    for (int row = r0; row < rend; row++) {
        int seg = (row >= T) ? 1 : 0;
        int t   = row - seg * T;
        int n_eff = seg * nsteps + min(t, nsteps);
        float s = (float)n_eff * C_DS;

        float th = w * s;
        float sth, cth;
        __sincosf(th, &sth, &cth);

        float A, Bc, Cz;              // sin/w, (1-cos)/w^2, (th-sin)/w^3
        if (th > 1e-3f) {
            A  = sth * (w * inv_w2);
            Bc = (1.f - cth) * inv_w2;
            Cz = (th - sth) * inv_w2 * (w * inv_w2);
        } else {                      // Taylor fallback (tiny/zero angle)
            float t2 = th * th;
            A  = s * (1.f - t2 * (1.f / 6.f));
            Bc = 0.5f * s * s * (1.f - t2 * (1.f / 12.f));
            Cz = s * s * s * (1.f / 6.f) * (1.f - t2 * (1.f / 20.f));
            cth = 1.f - 0.5f * t2;
        }

        // Protect previous row's drain reads before re-staging (warp-local).
        __syncwarp();

        if (active) {
            srow[0] = make_float2(Bc * uy,        -Bc * ux);            // r.x, r.y
            srow[1] = make_float2(s - Cz * w2,    1.f - Bc * uy * uy);  // r.z, R00
            srow[2] = make_float2(Bc * uxuy,      A * uy);              // R01, R02
            srow[3] = make_float2(Bc * uxuy,      1.f - Bc * ux * ux);  // R10, R11
            srow[4] = make_float2(-A * ux,        -A * uy);             // R12, R20
            srow[5] = make_float2(A * ux,         cth);                 // R21, R22
            srow[6] = make_float2(ux,             uy);
        }
        __syncwarp();   // warp's slice staged

        // Drain warp slice: 112 float4 = 3*32 + 16, contiguous in gmem.
        size_t base = ((size_t)row * (size_t)B + (size_t)wb0) * 14;
        if (wfull) {
            float4* o4 = (float4*)(out + base);
#pragma unroll
            for (int i = 0; i < 3; i++)
                __stcs(&o4[lane + i * 32], wslice4[lane + i * 32]);
            if (lane < (WSLICE4 - 96))
                __stcs(&o4[lane + 96], wslice4[lane + 96]);
        } else if (wvalid > 0) {
            const float* ws = (const float*)wslice4;
            int rowfloats = wvalid * 14;
            for (int f = lane; f < rowfloats; f += 32)
                out[base + f] = ws[f];
        }
    }
}

extern "C" void kernel_launch(void* const* d_in, const int* in_sizes, int n_in,
                              void* d_out, int out_size) {
    const float* actions = (const float*)d_in[0];
    float* out = (float*)d_out;

    int B = in_sizes[0] / 6;                 // 262144
    int T = out_size / (2 * B * 14);         // time steps per segment (incl. t=0)

    dim3 grid((B + TPB - 1) / TPB, NSPLIT);
    ode_forward_kernel<<<grid, TPB>>>(actions, out, B, T);
}

// round 16
// speedup vs baseline: 1.2626x; 1.0292x over previous
#include <cuda_runtime.h>
#include <cuda_bf16.h>

// Problem constants (from reference)
#define C_L0 0.05f
#define C_D  0.0075f
#define C_DS 0.005f

#define TPB 256            // batch elems per block == threads per block
#define ROWF (TPB * 14)    // floats per staged time-row (3584)
#define WSLICE4 (32 * 14 / 4)  // float4s per warp slice per row (112)
#define NSPLIT 8           // row-range splits per batch chunk (wave balance)

// Closed-form trajectory: with (ux,uy) constant (both segments use
// actions[:,0:3] due to the reference's end-of-loop update quirk), the ODE is
// linear with constant generator w_hat, axis w=(ux,uy,0):
//   R(s) = I + sin(th)/w * w_hat + (1-cos th)/w^2 * w_hat^2,  th = |w| s
//   r(s) = ( (1-cos th)/w^2 * uy, -(1-cos th)/w^2 * ux, s - (th - sin th)/|w| )
// Row (seg,t) = state after n_eff = seg*nsteps + min(t,nsteps) steps (frozen
// beyond nsteps by the reference's masking). Deviation from RK4 ~1e-5 abs,
// far under the 1e-3 tolerance.
//
// Structure: warp-autonomous pipelining (no block barriers); the 2T rows are
// split across NSPLIT CTAs per batch chunk (balanced) so the grid runs in ~7
// dense waves with a ~92%-full last wave (at NSPLIT=4 the last of 3.5 waves
// was only 46% full -> ~13% idle tail).
__global__ void __launch_bounds__(TPB)
ode_forward_kernel(const float* __restrict__ act, float* __restrict__ out, int B, int T) {
    __shared__ __align__(16) float sbuf[ROWF];   // single buffer; warp-private slices

    int b0 = blockIdx.x * TPB;
    int b  = b0 + threadIdx.x;
    int wid  = threadIdx.x >> 5;
    int lane = threadIdx.x & 31;
    bool active = (b < B);

    float a0 = 0.f, a1 = 0.f, a2 = 0.f;
    if (active) {
        a0 = __ldg(&act[(size_t)b * 6 + 0]);
        a1 = __ldg(&act[(size_t)b * 6 + 1]);
        a2 = __ldg(&act[(size_t)b * 6 + 2]);
    }

    float l  = C_L0 + a0;
    float ux = a2 / (-(l * C_D));
    float uy = a1 / (l * C_D);
    int nsteps = min((int)floorf(l / C_DS), T - 1);

    float w2 = fmaf(ux, ux, uy * uy);
    float w  = sqrtf(w2);
    float inv_w2 = 1.f / w2;          // actions ~U(0,1)*0.01 -> w >> 0 generically
    float uxuy   = ux * uy;

    // Warp-private smem slice: batch-linear within the block's row image.
    float2* srow = (float2*)&sbuf[(size_t)threadIdx.x * 14];
    const float4* wslice4 = (const float4*)&sbuf[(size_t)wid * 32 * 14];

    int wb0 = b0 + wid * 32;
    int wvalid = min(32, max(0, B - wb0));
    bool wfull = (wvalid == 32);

    // This CTA's balanced row range: 3 or 4 rows each for T2=26, NSPLIT=8.
    int T2 = 2 * T;
    int r0   = (blockIdx.y * T2) / NSPLIT;
    int rend = ((blockIdx.y + 1) * T2) / NSPLIT;

    for (int row = r0; row < rend; row++) {
        int seg = (row >= T) ? 1 : 0;
        int t   = row - seg * T;
        int n_eff = seg * nsteps + min(t, nsteps);
        float s = (float)n_eff * C_DS;

        float th = w * s;
        float sth, cth;
        __sincosf(th, &sth, &cth);

        float A, Bc, Cz;              // sin/w, (1-cos)/w^2, (th-sin)/w^3
        if (th > 1e-3f) {
            A  = sth * (w * inv_w2);
            Bc = (1.f - cth) * inv_w2;
            Cz = (th - sth) * inv_w2 * (w * inv_w2);
        } else {                      // Taylor fallback (tiny/zero angle)
            float t2 = th * th;
            A  = s * (1.f - t2 * (1.f / 6.f));
            Bc = 0.5f * s * s * (1.f - t2 * (1.f / 12.f));
            Cz = s * s * s * (1.f / 6.f) * (1.f - t2 * (1.f / 20.f));
            cth = 1.f - 0.5f * t2;
        }

        // Protect previous row's drain reads before re-staging (warp-local).
        __syncwarp();

        if (active) {
            srow[0] = make_float2(Bc * uy,        -Bc * ux);            // r.x, r.y
            srow[1] = make_float2(s - Cz * w2,    1.f - Bc * uy * uy);  // r.z, R00
            srow[2] = make_float2(Bc * uxuy,      A * uy);              // R01, R02
            srow[3] = make_float2(Bc * uxuy,      1.f - Bc * ux * ux);  // R10, R11
            srow[4] = make_float2(-A * ux,        -A * uy);             // R12, R20
            srow[5] = make_float2(A * ux,         cth);                 // R21, R22
            srow[6] = make_float2(ux,             uy);
        }
        __syncwarp();   // warp's slice staged

        // Drain warp slice: 112 float4 = 3*32 + 16, contiguous in gmem.
        size_t base = ((size_t)row * (size_t)B + (size_t)wb0) * 14;
        if (wfull) {
            float4* o4 = (float4*)(out + base);
#pragma unroll
            for (int i = 0; i < 3; i++)
                __stcs(&o4[lane + i * 32], wslice4[lane + i * 32]);
            if (lane < (WSLICE4 - 96))
                __stcs(&o4[lane + 96], wslice4[lane + 96]);
        } else if (wvalid > 0) {
            const float* ws = (const float*)wslice4;
            int rowfloats = wvalid * 14;
            for (int f = lane; f < rowfloats; f += 32)
                out[base + f] = ws[f];
        }
    }
}

extern "C" void kernel_launch(void* const* d_in, const int* in_sizes, int n_in,
                              void* d_out, int out_size) {
    const float* actions = (const float*)d_in[0];
    float* out = (float*)d_out;

    int B = in_sizes[0] / 6;                 // 262144
    int T = out_size / (2 * B * 14);         // time steps per segment (incl. t=0)

    dim3 grid((B + TPB - 1) / TPB, NSPLIT);
    ode_forward_kernel<<<grid, TPB>>>(actions, out, B, T);
}